// round 1
// baseline (speedup 1.0000x reference)
#include <cuda_runtime.h>
#include <math.h>

// ---------------------------------------------------------------------------
// CReST loss:
//   out[0] = loss = Lx + Lu
//   out[1] = Lx   (mean CE of logits_x vs targets_x)
//   out[2] = Lu   (mean over N of CE(logits_su, t_m) * conf * rebal)
//   out[3..3+N) = max_probs (max of softmax(logits_wu))
// ---------------------------------------------------------------------------

#define FULLMASK 0xffffffffu
#define BLK 128
#define MAXC 1024
#define SEG 256
#define MAXN 65536
#define NSEG_MAX (MAXN / SEG)
#define MAXBX 32768

__device__ int           g_tm[MAXN];
__device__ unsigned char g_mask[MAXN];
__device__ float         g_ce_x[MAXBX];
__device__ float         g_ce_u[MAXN];
__device__ int           g_seg_counts[NSEG_MAX][MAXC];
__device__ int           g_seg_off[NSEG_MAX][MAXC];
__device__ int           g_bn[MAXC];

// ---- block reductions for 128-thread blocks (4 warps) ----------------------
__device__ __forceinline__ float blockReduceSum128(float v) {
    __shared__ float s[4];
    __syncthreads();  // protect shared reuse across consecutive calls
    #pragma unroll
    for (int o = 16; o; o >>= 1) v += __shfl_down_sync(FULLMASK, v, o);
    int lane = threadIdx.x & 31, w = threadIdx.x >> 5;
    if (lane == 0) s[w] = v;
    __syncthreads();
    if (w == 0) {
        v = (lane < 4) ? s[lane] : 0.f;
        #pragma unroll
        for (int o = 2; o; o >>= 1) v += __shfl_down_sync(FULLMASK, v, o);
        if (lane == 0) s[0] = v;
    }
    __syncthreads();
    return s[0];
}

__device__ __forceinline__ float blockReduceMax128(float v) {
    __shared__ float s[4];
    __syncthreads();
    #pragma unroll
    for (int o = 16; o; o >>= 1) v = fmaxf(v, __shfl_down_sync(FULLMASK, v, o));
    int lane = threadIdx.x & 31, w = threadIdx.x >> 5;
    if (lane == 0) s[w] = v;
    __syncthreads();
    if (w == 0) {
        v = (lane < 4) ? s[lane] : -INFINITY;
        #pragma unroll
        for (int o = 2; o; o >>= 1) v = fmaxf(v, __shfl_down_sync(FULLMASK, v, o));
        if (lane == 0) s[0] = v;
    }
    __syncthreads();
    return s[0];
}

// ---- kernel 1: weak-aug logits -> max_probs, t_m ---------------------------
__global__ void k_wu(const float* __restrict__ lwu, int C,
                     float* __restrict__ maxp_out) {
    int row = blockIdx.x;
    const float* rowp = lwu + (size_t)row * C;
    const float4* rp = (const float4*)rowp;
    int n4 = C >> 2;
    int tail = C & 3;

    float4 v[2];
    float bv = -INFINITY;
    int bi = 0x3fffffff;
    #pragma unroll
    for (int u = 0; u < 2; u++) {
        int k = threadIdx.x + u * BLK;
        if (k < n4) {
            v[u] = rp[k];
            int j = 4 * k;
            if (v[u].x > bv) { bv = v[u].x; bi = j; }
            if (v[u].y > bv) { bv = v[u].y; bi = j + 1; }
            if (v[u].z > bv) { bv = v[u].z; bi = j + 2; }
            if (v[u].w > bv) { bv = v[u].w; bi = j + 3; }
        }
    }
    float tv = -INFINITY; int tj = -1;
    if (tail && threadIdx.x < tail) {
        tj = 4 * n4 + threadIdx.x;
        tv = rowp[tj];
        if (tv > bv) { bv = tv; bi = tj; }
    }

    // (val, idx) reduce with first-index tie-break
    #pragma unroll
    for (int o = 16; o; o >>= 1) {
        float ov = __shfl_down_sync(FULLMASK, bv, o);
        int   oi = __shfl_down_sync(FULLMASK, bi, o);
        if (ov > bv || (ov == bv && oi < bi)) { bv = ov; bi = oi; }
    }
    __shared__ float sv[4]; __shared__ int si[4];
    int lane = threadIdx.x & 31, w = threadIdx.x >> 5;
    if (lane == 0) { sv[w] = bv; si[w] = bi; }
    __syncthreads();
    if (w == 0) {
        bv = (lane < 4) ? sv[lane] : -INFINITY;
        bi = (lane < 4) ? si[lane] : 0x3fffffff;
        #pragma unroll
        for (int o = 2; o; o >>= 1) {
            float ov = __shfl_down_sync(FULLMASK, bv, o);
            int   oi = __shfl_down_sync(FULLMASK, bi, o);
            if (ov > bv || (ov == bv && oi < bi)) { bv = ov; bi = oi; }
        }
        if (lane == 0) { sv[0] = bv; si[0] = bi; }
    }
    __syncthreads();
    float maxv = sv[0];
    int argi = si[0];

    float s = 0.f;
    #pragma unroll
    for (int u = 0; u < 2; u++) {
        int k = threadIdx.x + u * BLK;
        if (k < n4) {
            s += __expf(v[u].x - maxv) + __expf(v[u].y - maxv)
               + __expf(v[u].z - maxv) + __expf(v[u].w - maxv);
        }
    }
    if (tj >= 0) s += __expf(tv - maxv);
    s = blockReduceSum128(s);

    if (threadIdx.x == 0) {
        float maxp = 1.0f / s;  // exp(maxv - lse), since max shifted term = 1
        maxp_out[row] = maxp;
        g_tm[row] = (maxp >= 0.95f) ? argi : 0;
    }
}

// ---- kernel 2: supervised CE per row ---------------------------------------
__global__ void k_x(const float* __restrict__ lx, int C,
                    const int* __restrict__ tgts) {
    int row = blockIdx.x;
    const float* rowp = lx + (size_t)row * C;
    const float4* rp = (const float4*)rowp;
    int n4 = C >> 2;
    int tail = C & 3;
    int tgt = tgts[row];
    __shared__ float stgt;

    float4 v[2];
    float m = -INFINITY;
    #pragma unroll
    for (int u = 0; u < 2; u++) {
        int k = threadIdx.x + u * BLK;
        if (k < n4) {
            v[u] = rp[k];
            int j = 4 * k;
            m = fmaxf(m, fmaxf(fmaxf(v[u].x, v[u].y), fmaxf(v[u].z, v[u].w)));
            if (tgt >= j && tgt < j + 4) {
                float t4[4] = {v[u].x, v[u].y, v[u].z, v[u].w};
                stgt = t4[tgt - j];
            }
        }
    }
    float tv = 0.f; int tj = -1;
    if (tail && threadIdx.x < tail) {
        tj = 4 * n4 + threadIdx.x;
        tv = rowp[tj];
        m = fmaxf(m, tv);
        if (tj == tgt) stgt = tv;
    }
    float maxv = blockReduceMax128(m);   // internal syncthreads orders stgt write

    float s = 0.f;
    #pragma unroll
    for (int u = 0; u < 2; u++) {
        int k = threadIdx.x + u * BLK;
        if (k < n4) {
            s += __expf(v[u].x - maxv) + __expf(v[u].y - maxv)
               + __expf(v[u].z - maxv) + __expf(v[u].w - maxv);
        }
    }
    if (tj >= 0) s += __expf(tv - maxv);
    s = blockReduceSum128(s);

    if (threadIdx.x == 0)
        g_ce_x[row] = maxv + logf(s) - stgt;
}

// ---- kernel 3: per-segment class histograms --------------------------------
__global__ void k_seghist(int N, int C) {
    __shared__ int h[MAXC];
    for (int c = threadIdx.x; c < C; c += blockDim.x) h[c] = 0;
    __syncthreads();
    int row = blockIdx.x * SEG + threadIdx.x;
    if (row < N) atomicAdd(&h[g_tm[row]], 1);
    __syncthreads();
    for (int c = threadIdx.x; c < C; c += blockDim.x)
        g_seg_counts[blockIdx.x][c] = h[c];
}

// ---- kernel 4: per-class exclusive scan over segments + bn -----------------
__global__ void k_scan(int nseg, int C, const float* __restrict__ gtp) {
    int c = blockIdx.x * blockDim.x + threadIdx.x;
    if (c >= C) return;
    int run = 0;
    for (int s = 0; s < nseg; s++) {
        g_seg_off[s][c] = run;
        run += g_seg_counts[s][c];
    }
    // round half-to-even, matching jnp.round / torch .round()
    g_bn[c] = (int)rintf((float)run * gtp[c]);
}

// ---- kernel 5: stable within-class rank + rebalance mask -------------------
__global__ void k_rank(int N) {
    __shared__ int stm[SEG];
    int r = threadIdx.x;
    int row = blockIdx.x * SEG + r;
    int myc = (row < N) ? g_tm[row] : -1;
    stm[r] = myc;
    __syncthreads();
    int local = 0;
    #pragma unroll 8
    for (int j = 0; j < SEG; j++) {
        if (j < r && stm[j] == myc) local++;
    }
    if (row < N) {
        int rank = g_seg_off[blockIdx.x][myc] + local;
        g_mask[row] = (unsigned char)((myc != 0) && (rank < g_bn[myc]));
    }
}

// ---- kernel 6: unsupervised CE, only for contributing rows -----------------
__global__ void k_su(const float* __restrict__ lsu, int C) {
    int row = blockIdx.x;
    if (!g_mask[row]) {
        if (threadIdx.x == 0) g_ce_u[row] = 0.f;
        return;  // skip HBM read for this row entirely
    }
    const float* rowp = lsu + (size_t)row * C;
    const float4* rp = (const float4*)rowp;
    int n4 = C >> 2;
    int tail = C & 3;
    int tgt = g_tm[row];
    __shared__ float stgt;

    float4 v[2];
    float m = -INFINITY;
    #pragma unroll
    for (int u = 0; u < 2; u++) {
        int k = threadIdx.x + u * BLK;
        if (k < n4) {
            v[u] = rp[k];
            int j = 4 * k;
            m = fmaxf(m, fmaxf(fmaxf(v[u].x, v[u].y), fmaxf(v[u].z, v[u].w)));
            if (tgt >= j && tgt < j + 4) {
                float t4[4] = {v[u].x, v[u].y, v[u].z, v[u].w};
                stgt = t4[tgt - j];
            }
        }
    }
    float tv = 0.f; int tj = -1;
    if (tail && threadIdx.x < tail) {
        tj = 4 * n4 + threadIdx.x;
        tv = rowp[tj];
        m = fmaxf(m, tv);
        if (tj == tgt) stgt = tv;
    }
    float maxv = blockReduceMax128(m);

    float s = 0.f;
    #pragma unroll
    for (int u = 0; u < 2; u++) {
        int k = threadIdx.x + u * BLK;
        if (k < n4) {
            s += __expf(v[u].x - maxv) + __expf(v[u].y - maxv)
               + __expf(v[u].z - maxv) + __expf(v[u].w - maxv);
        }
    }
    if (tj >= 0) s += __expf(tv - maxv);
    s = blockReduceSum128(s);

    if (threadIdx.x == 0)
        g_ce_u[row] = maxv + logf(s) - stgt;
}

// ---- kernel 7: deterministic final reduction -------------------------------
__global__ void k_reduce(int Bx, int N, float* __restrict__ out) {
    __shared__ float sh[1024];
    __shared__ float lx_s;
    int tid = threadIdx.x;

    float a = 0.f;
    for (int i = tid; i < Bx; i += 1024) a += g_ce_x[i];
    sh[tid] = a;
    __syncthreads();
    for (int o = 512; o; o >>= 1) {
        if (tid < o) sh[tid] += sh[tid + o];
        __syncthreads();
    }
    if (tid == 0) lx_s = sh[0];
    __syncthreads();

    float b = 0.f;
    for (int i = tid; i < N; i += 1024) b += g_ce_u[i];
    sh[tid] = b;
    __syncthreads();
    for (int o = 512; o; o >>= 1) {
        if (tid < o) sh[tid] += sh[tid + o];
        __syncthreads();
    }
    if (tid == 0) {
        float Lx = lx_s / (float)Bx;
        float Lu = sh[0] / (float)N;
        out[0] = Lx + Lu;  // LAMBDA_U = 1.0
        out[1] = Lx;
        out[2] = Lu;
    }
}

// ---------------------------------------------------------------------------
extern "C" void kernel_launch(void* const* d_in, const int* in_sizes, int n_in,
                              void* d_out, int out_size) {
    const float* lx  = (const float*)d_in[0];
    const float* lwu = (const float*)d_in[1];
    const float* lsu = (const float*)d_in[2];
    const int*   tx  = (const int*)d_in[3];
    const float* gtp = (const float*)d_in[4];
    // d_in[5] = t (unused)

    int Bx = in_sizes[3];
    int C  = in_sizes[4];
    int N  = in_sizes[1] / C;
    int nseg = (N + SEG - 1) / SEG;

    float* out = (float*)d_out;

    k_wu<<<N, BLK>>>(lwu, C, out + 3);
    k_x<<<Bx, BLK>>>(lx, C, tx);
    k_seghist<<<nseg, SEG>>>(N, C);
    k_scan<<<(C + 255) / 256, 256>>>(nseg, C, gtp);
    k_rank<<<nseg, SEG>>>(N);
    k_su<<<N, BLK>>>(lsu, C);
    k_reduce<<<1, 1024>>>(Bx, N, out);
}

// round 2
// speedup vs baseline: 1.4068x; 1.4068x over previous
#include <cuda_runtime.h>
#include <math.h>

// ---------------------------------------------------------------------------
// CReST loss:
//   out[0] = loss = Lx + Lu
//   out[1] = Lx   (mean CE of logits_x vs targets_x)
//   out[2] = Lu   (mean over N of CE(logits_su, t_m) * conf * rebal)
//   out[3..3+N) = max_probs (max of softmax(logits_wu))
// ---------------------------------------------------------------------------

#define FULLMASK 0xffffffffu
#define BLK 128
#define MAXC 1024
#define SEG 256
#define MAXN 65536
#define NSEG_MAX (MAXN / SEG)
#define MAXBX 32768

__device__ int           g_tm[MAXN];
__device__ unsigned char g_mask[MAXN];
__device__ float         g_ce_x[MAXBX];
__device__ float         g_ce_u[MAXN];
__device__ int           g_seg_counts[NSEG_MAX][MAXC];
__device__ int           g_seg_off[NSEG_MAX][MAXC];
__device__ int           g_bn[MAXC];

// ---- block reductions for 128-thread blocks (4 warps) ----------------------
__device__ __forceinline__ float blockReduceSum128(float v) {
    __shared__ float s[4];
    __syncthreads();  // protect shared reuse across consecutive calls
    #pragma unroll
    for (int o = 16; o; o >>= 1) v += __shfl_down_sync(FULLMASK, v, o);
    int lane = threadIdx.x & 31, w = threadIdx.x >> 5;
    if (lane == 0) s[w] = v;
    __syncthreads();
    if (w == 0) {
        v = (lane < 4) ? s[lane] : 0.f;
        #pragma unroll
        for (int o = 2; o; o >>= 1) v += __shfl_down_sync(FULLMASK, v, o);
        if (lane == 0) s[0] = v;
    }
    __syncthreads();
    return s[0];
}

__device__ __forceinline__ float blockReduceMax128(float v) {
    __shared__ float s[4];
    __syncthreads();
    #pragma unroll
    for (int o = 16; o; o >>= 1) v = fmaxf(v, __shfl_down_sync(FULLMASK, v, o));
    int lane = threadIdx.x & 31, w = threadIdx.x >> 5;
    if (lane == 0) s[w] = v;
    __syncthreads();
    if (w == 0) {
        v = (lane < 4) ? s[lane] : -INFINITY;
        #pragma unroll
        for (int o = 2; o; o >>= 1) v = fmaxf(v, __shfl_down_sync(FULLMASK, v, o));
        if (lane == 0) s[0] = v;
    }
    __syncthreads();
    return s[0];
}

// ---- kernel 1: weak-aug logits -> max_probs, t_m ---------------------------
__global__ void k_wu(const float* __restrict__ lwu, int C,
                     float* __restrict__ maxp_out) {
    int row = blockIdx.x;
    const float* rowp = lwu + (size_t)row * C;
    const float4* rp = (const float4*)rowp;
    int n4 = C >> 2;
    int tail = C & 3;

    float4 v[2];
    float bv = -INFINITY;
    int bi = 0x3fffffff;
    #pragma unroll
    for (int u = 0; u < 2; u++) {
        int k = threadIdx.x + u * BLK;
        if (k < n4) {
            v[u] = rp[k];
            int j = 4 * k;
            if (v[u].x > bv) { bv = v[u].x; bi = j; }
            if (v[u].y > bv) { bv = v[u].y; bi = j + 1; }
            if (v[u].z > bv) { bv = v[u].z; bi = j + 2; }
            if (v[u].w > bv) { bv = v[u].w; bi = j + 3; }
        }
    }
    float tv = -INFINITY; int tj = -1;
    if (tail && threadIdx.x < tail) {
        tj = 4 * n4 + threadIdx.x;
        tv = rowp[tj];
        if (tv > bv) { bv = tv; bi = tj; }
    }

    // (val, idx) reduce with first-index tie-break
    #pragma unroll
    for (int o = 16; o; o >>= 1) {
        float ov = __shfl_down_sync(FULLMASK, bv, o);
        int   oi = __shfl_down_sync(FULLMASK, bi, o);
        if (ov > bv || (ov == bv && oi < bi)) { bv = ov; bi = oi; }
    }
    __shared__ float sv[4]; __shared__ int si[4];
    int lane = threadIdx.x & 31, w = threadIdx.x >> 5;
    if (lane == 0) { sv[w] = bv; si[w] = bi; }
    __syncthreads();
    if (w == 0) {
        bv = (lane < 4) ? sv[lane] : -INFINITY;
        bi = (lane < 4) ? si[lane] : 0x3fffffff;
        #pragma unroll
        for (int o = 2; o; o >>= 1) {
            float ov = __shfl_down_sync(FULLMASK, bv, o);
            int   oi = __shfl_down_sync(FULLMASK, bi, o);
            if (ov > bv || (ov == bv && oi < bi)) { bv = ov; bi = oi; }
        }
        if (lane == 0) { sv[0] = bv; si[0] = bi; }
    }
    __syncthreads();
    float maxv = sv[0];
    int argi = si[0];

    float s = 0.f;
    #pragma unroll
    for (int u = 0; u < 2; u++) {
        int k = threadIdx.x + u * BLK;
        if (k < n4) {
            s += __expf(v[u].x - maxv) + __expf(v[u].y - maxv)
               + __expf(v[u].z - maxv) + __expf(v[u].w - maxv);
        }
    }
    if (tj >= 0) s += __expf(tv - maxv);
    s = blockReduceSum128(s);

    if (threadIdx.x == 0) {
        float maxp = 1.0f / s;  // exp(maxv - lse), since max shifted term = 1
        maxp_out[row] = maxp;
        g_tm[row] = (maxp >= 0.95f) ? argi : 0;
    }
}

// ---- kernel 2: supervised CE per row ---------------------------------------
__global__ void k_x(const float* __restrict__ lx, int C,
                    const int* __restrict__ tgts) {
    int row = blockIdx.x;
    const float* rowp = lx + (size_t)row * C;
    const float4* rp = (const float4*)rowp;
    int n4 = C >> 2;
    int tail = C & 3;
    int tgt = tgts[row];
    __shared__ float stgt;

    float4 v[2];
    float m = -INFINITY;
    #pragma unroll
    for (int u = 0; u < 2; u++) {
        int k = threadIdx.x + u * BLK;
        if (k < n4) {
            v[u] = rp[k];
            int j = 4 * k;
            m = fmaxf(m, fmaxf(fmaxf(v[u].x, v[u].y), fmaxf(v[u].z, v[u].w)));
            if (tgt >= j && tgt < j + 4) {
                float t4[4] = {v[u].x, v[u].y, v[u].z, v[u].w};
                stgt = t4[tgt - j];
            }
        }
    }
    float tv = 0.f; int tj = -1;
    if (tail && threadIdx.x < tail) {
        tj = 4 * n4 + threadIdx.x;
        tv = rowp[tj];
        m = fmaxf(m, tv);
        if (tj == tgt) stgt = tv;
    }
    float maxv = blockReduceMax128(m);   // internal syncthreads orders stgt write

    float s = 0.f;
    #pragma unroll
    for (int u = 0; u < 2; u++) {
        int k = threadIdx.x + u * BLK;
        if (k < n4) {
            s += __expf(v[u].x - maxv) + __expf(v[u].y - maxv)
               + __expf(v[u].z - maxv) + __expf(v[u].w - maxv);
        }
    }
    if (tj >= 0) s += __expf(tv - maxv);
    s = blockReduceSum128(s);

    if (threadIdx.x == 0)
        g_ce_x[row] = maxv + logf(s) - stgt;
}

// ---- kernel 3: per-segment class histograms --------------------------------
__global__ void k_seghist(int N, int C) {
    __shared__ int h[MAXC];
    for (int c = threadIdx.x; c < C; c += blockDim.x) h[c] = 0;
    __syncthreads();
    int row = blockIdx.x * SEG + threadIdx.x;
    if (row < N) atomicAdd(&h[g_tm[row]], 1);
    __syncthreads();
    for (int c = threadIdx.x; c < C; c += blockDim.x)
        g_seg_counts[blockIdx.x][c] = h[c];
}

// ---- kernel 4: per-class exclusive scan over segments + bn -----------------
// One block per class; 256 threads scan across (up to) 256 segments in shared
// memory. Replaces the serial per-thread global-latency loop that was 119us.
__global__ void k_scan(int nseg, const float* __restrict__ gtp) {
    int c = blockIdx.x;
    int s = threadIdx.x;
    __shared__ int sh[SEG];

    int v = (s < nseg) ? g_seg_counts[s][c] : 0;
    sh[s] = v;
    __syncthreads();

    // Hillis-Steele inclusive scan over 256 elements
    #pragma unroll
    for (int o = 1; o < SEG; o <<= 1) {
        int t = (s >= o) ? sh[s - o] : 0;
        __syncthreads();
        sh[s] += t;
        __syncthreads();
    }
    int incl = sh[s];
    if (s < nseg) g_seg_off[s][c] = incl - v;   // exclusive
    if (s == SEG - 1) {
        // total count of class c = inclusive scan at last slot
        // round half-to-even, matching jnp.round / torch .round()
        g_bn[c] = (int)rintf((float)incl * gtp[c]);
    }
}

// ---- kernel 5: stable within-class rank + rebalance mask -------------------
__global__ void k_rank(int N) {
    __shared__ int stm[SEG];
    int r = threadIdx.x;
    int row = blockIdx.x * SEG + r;
    int myc = (row < N) ? g_tm[row] : -1;
    stm[r] = myc;
    __syncthreads();
    int local = 0;
    #pragma unroll 8
    for (int j = 0; j < SEG; j++) {
        if (j < r && stm[j] == myc) local++;
    }
    if (row < N) {
        int rank = g_seg_off[blockIdx.x][myc] + local;
        g_mask[row] = (unsigned char)((myc != 0) && (rank < g_bn[myc]));
    }
}

// ---- kernel 6: unsupervised CE, only for contributing rows -----------------
__global__ void k_su(const float* __restrict__ lsu, int C) {
    int row = blockIdx.x;
    if (!g_mask[row]) {
        if (threadIdx.x == 0) g_ce_u[row] = 0.f;
        return;  // skip HBM read for this row entirely
    }
    const float* rowp = lsu + (size_t)row * C;
    const float4* rp = (const float4*)rowp;
    int n4 = C >> 2;
    int tail = C & 3;
    int tgt = g_tm[row];
    __shared__ float stgt;

    float4 v[2];
    float m = -INFINITY;
    #pragma unroll
    for (int u = 0; u < 2; u++) {
        int k = threadIdx.x + u * BLK;
        if (k < n4) {
            v[u] = rp[k];
            int j = 4 * k;
            m = fmaxf(m, fmaxf(fmaxf(v[u].x, v[u].y), fmaxf(v[u].z, v[u].w)));
            if (tgt >= j && tgt < j + 4) {
                float t4[4] = {v[u].x, v[u].y, v[u].z, v[u].w};
                stgt = t4[tgt - j];
            }
        }
    }
    float tv = 0.f; int tj = -1;
    if (tail && threadIdx.x < tail) {
        tj = 4 * n4 + threadIdx.x;
        tv = rowp[tj];
        m = fmaxf(m, tv);
        if (tj == tgt) stgt = tv;
    }
    float maxv = blockReduceMax128(m);

    float s = 0.f;
    #pragma unroll
    for (int u = 0; u < 2; u++) {
        int k = threadIdx.x + u * BLK;
        if (k < n4) {
            s += __expf(v[u].x - maxv) + __expf(v[u].y - maxv)
               + __expf(v[u].z - maxv) + __expf(v[u].w - maxv);
        }
    }
    if (tj >= 0) s += __expf(tv - maxv);
    s = blockReduceSum128(s);

    if (threadIdx.x == 0)
        g_ce_u[row] = maxv + logf(s) - stgt;
}

// ---- kernel 7: deterministic final reduction -------------------------------
__global__ void k_reduce(int Bx, int N, float* __restrict__ out) {
    __shared__ float sh[1024];
    __shared__ float lx_s;
    int tid = threadIdx.x;

    float a = 0.f;
    for (int i = tid; i < Bx; i += 1024) a += g_ce_x[i];
    sh[tid] = a;
    __syncthreads();
    for (int o = 512; o; o >>= 1) {
        if (tid < o) sh[tid] += sh[tid + o];
        __syncthreads();
    }
    if (tid == 0) lx_s = sh[0];
    __syncthreads();

    float b = 0.f;
    for (int i = tid; i < N; i += 1024) b += g_ce_u[i];
    sh[tid] = b;
    __syncthreads();
    for (int o = 512; o; o >>= 1) {
        if (tid < o) sh[tid] += sh[tid + o];
        __syncthreads();
    }
    if (tid == 0) {
        float Lx = lx_s / (float)Bx;
        float Lu = sh[0] / (float)N;
        out[0] = Lx + Lu;  // LAMBDA_U = 1.0
        out[1] = Lx;
        out[2] = Lu;
    }
}

// ---------------------------------------------------------------------------
extern "C" void kernel_launch(void* const* d_in, const int* in_sizes, int n_in,
                              void* d_out, int out_size) {
    const float* lx  = (const float*)d_in[0];
    const float* lwu = (const float*)d_in[1];
    const float* lsu = (const float*)d_in[2];
    const int*   tx  = (const int*)d_in[3];
    const float* gtp = (const float*)d_in[4];
    // d_in[5] = t (unused)

    int Bx = in_sizes[3];
    int C  = in_sizes[4];
    int N  = in_sizes[1] / C;
    int nseg = (N + SEG - 1) / SEG;

    float* out = (float*)d_out;

    k_wu<<<N, BLK>>>(lwu, C, out + 3);
    k_x<<<Bx, BLK>>>(lx, C, tx);
    k_seghist<<<nseg, SEG>>>(N, C);
    k_scan<<<C, SEG>>>(nseg, gtp);
    k_rank<<<nseg, SEG>>>(N);
    k_su<<<N, BLK>>>(lsu, C);
    k_reduce<<<1, 1024>>>(Bx, N, out);
}

// round 3
// speedup vs baseline: 1.6148x; 1.1478x over previous
#include <cuda_runtime.h>
#include <math.h>

// ---------------------------------------------------------------------------
// CReST loss. Warp-per-row softmax kernels (no barriers), fused wu+x pass.
//   out[0]=loss, out[1]=Lx, out[2]=Lu, out[3..3+N)=max_probs
// ---------------------------------------------------------------------------

#define FULLMASK 0xffffffffu
#define MAXC 1024
#define SEG 256
#define MAXN 65536
#define NSEG_MAX (MAXN / SEG)
#define MAXBX 32768
#define WPB 8              // warps per block in row kernels

__device__ int           g_tm[MAXN];
__device__ unsigned char g_mask[MAXN];
__device__ float         g_ce_x[MAXBX];
__device__ float         g_ce_u[MAXN];
__device__ int           g_seg_counts[NSEG_MAX][MAXC];
__device__ int           g_seg_off[NSEG_MAX][MAXC];
__device__ int           g_bn[MAXC];

// ---- fused kernel: wu rows (maxp + t_m) and x rows (supervised CE) ---------
// One warp per row. C <= MAXC assumed (8 float4 per lane covers C<=1024).
__global__ void k_rows(const float* __restrict__ lwu,
                       const float* __restrict__ lx,
                       const int* __restrict__ tgts,
                       int C, int N, int Bx,
                       float* __restrict__ maxp_out) {
    int lane = threadIdx.x & 31;
    int gw = blockIdx.x * WPB + (threadIdx.x >> 5);
    int n4 = C >> 2;
    int tail = C & 3;

    if (gw < N) {
        // ---- weak-aug row: max_probs + pseudo target ----
        const float* rowp = lwu + (size_t)gw * C;
        const float4* rp = (const float4*)rowp;

        float4 v[8];
        float bv = -INFINITY;
        int bi = 0x3fffffff;
        #pragma unroll
        for (int u = 0; u < 8; u++) {
            int k = lane + u * 32;
            if (k < n4) {
                v[u] = rp[k];
                int j = 4 * k;
                if (v[u].x > bv) { bv = v[u].x; bi = j; }
                if (v[u].y > bv) { bv = v[u].y; bi = j + 1; }
                if (v[u].z > bv) { bv = v[u].z; bi = j + 2; }
                if (v[u].w > bv) { bv = v[u].w; bi = j + 3; }
            }
        }
        float tv = -INFINITY; int tj = -1;
        if (tail && lane < tail) {
            tj = 4 * n4 + lane;
            tv = rowp[tj];
            if (tv > bv) { bv = tv; bi = tj; }
        }

        // butterfly (val,idx) reduce, first-index tie-break; all lanes converge
        #pragma unroll
        for (int o = 16; o; o >>= 1) {
            float ov = __shfl_xor_sync(FULLMASK, bv, o);
            int   oi = __shfl_xor_sync(FULLMASK, bi, o);
            if (ov > bv || (ov == bv && oi < bi)) { bv = ov; bi = oi; }
        }
        float maxv = bv;

        float s = 0.f;
        #pragma unroll
        for (int u = 0; u < 8; u++) {
            int k = lane + u * 32;
            if (k < n4) {
                s += __expf(v[u].x - maxv) + __expf(v[u].y - maxv)
                   + __expf(v[u].z - maxv) + __expf(v[u].w - maxv);
            }
        }
        if (tj >= 0) s += __expf(tv - maxv);
        #pragma unroll
        for (int o = 16; o; o >>= 1) s += __shfl_xor_sync(FULLMASK, s, o);

        if (lane == 0) {
            float maxp = 1.0f / s;  // exp(maxv - lse)
            maxp_out[gw] = maxp;
            g_tm[gw] = (maxp >= 0.95f) ? bi : 0;
        }
    } else if (gw < N + Bx) {
        // ---- supervised row: CE vs targets ----
        int row = gw - N;
        const float* rowp = lx + (size_t)row * C;
        const float4* rp = (const float4*)rowp;
        int tgt = tgts[row];

        float4 v[8];
        float m = -INFINITY;
        float tval = 0.f;
        #pragma unroll
        for (int u = 0; u < 8; u++) {
            int k = lane + u * 32;
            if (k < n4) {
                v[u] = rp[k];
                int j = 4 * k;
                m = fmaxf(m, fmaxf(fmaxf(v[u].x, v[u].y), fmaxf(v[u].z, v[u].w)));
                if (tgt >= j && tgt < j + 4) {
                    float t4[4] = {v[u].x, v[u].y, v[u].z, v[u].w};
                    tval = t4[tgt - j];
                }
            }
        }
        float tv = 0.f; int tj = -1;
        if (tail && lane < tail) {
            tj = 4 * n4 + lane;
            tv = rowp[tj];
            m = fmaxf(m, tv);
            if (tj == tgt) tval = tv;
        }
        #pragma unroll
        for (int o = 16; o; o >>= 1) {
            m = fmaxf(m, __shfl_xor_sync(FULLMASK, m, o));
            tval += __shfl_xor_sync(FULLMASK, tval, o);  // exactly one lane nonzero
        }

        float s = 0.f;
        #pragma unroll
        for (int u = 0; u < 8; u++) {
            int k = lane + u * 32;
            if (k < n4) {
                s += __expf(v[u].x - m) + __expf(v[u].y - m)
                   + __expf(v[u].z - m) + __expf(v[u].w - m);
            }
        }
        if (tj >= 0) s += __expf(tv - m);
        #pragma unroll
        for (int o = 16; o; o >>= 1) s += __shfl_xor_sync(FULLMASK, s, o);

        if (lane == 0)
            g_ce_x[row] = m + logf(s) - tval;
    }
}

// ---- per-segment class histograms -------------------------------------------
__global__ void k_seghist(int N, int C) {
    __shared__ int h[MAXC];
    for (int c = threadIdx.x; c < C; c += blockDim.x) h[c] = 0;
    __syncthreads();
    int row = blockIdx.x * SEG + threadIdx.x;
    if (row < N) atomicAdd(&h[g_tm[row]], 1);
    __syncthreads();
    for (int c = threadIdx.x; c < C; c += blockDim.x)
        g_seg_counts[blockIdx.x][c] = h[c];
}

// ---- per-class exclusive scan over segments + bn ----------------------------
__global__ void k_scan(int nseg, const float* __restrict__ gtp) {
    int c = blockIdx.x;
    int s = threadIdx.x;
    __shared__ int sh[SEG];

    int v = (s < nseg) ? g_seg_counts[s][c] : 0;
    sh[s] = v;
    __syncthreads();

    #pragma unroll
    for (int o = 1; o < SEG; o <<= 1) {
        int t = (s >= o) ? sh[s - o] : 0;
        __syncthreads();
        sh[s] += t;
        __syncthreads();
    }
    int incl = sh[s];
    if (s < nseg) g_seg_off[s][c] = incl - v;   // exclusive
    if (s == SEG - 1) {
        // round half-to-even, matching jnp.round
        g_bn[c] = (int)rintf((float)incl * gtp[c]);
    }
}

// ---- stable within-class rank + rebalance mask ------------------------------
__global__ void k_rank(int N) {
    __shared__ int stm[SEG];
    int r = threadIdx.x;
    int row = blockIdx.x * SEG + r;
    int myc = (row < N) ? g_tm[row] : -1;
    stm[r] = myc;
    __syncthreads();
    int local = 0;
    #pragma unroll 8
    for (int j = 0; j < SEG; j++) {
        if (j < r && stm[j] == myc) local++;
    }
    if (row < N) {
        int rank = g_seg_off[blockIdx.x][myc] + local;
        g_mask[row] = (unsigned char)((myc != 0) && (rank < g_bn[myc]));
    }
}

// ---- unsupervised CE, warp per row, skip masked-out rows --------------------
__global__ void k_su(const float* __restrict__ lsu, int C, int N) {
    int lane = threadIdx.x & 31;
    int row = blockIdx.x * WPB + (threadIdx.x >> 5);
    if (row >= N) return;
    if (!g_mask[row]) {
        if (lane == 0) g_ce_u[row] = 0.f;
        return;  // per-warp exit, no barriers in this kernel
    }
    const float* rowp = lsu + (size_t)row * C;
    const float4* rp = (const float4*)rowp;
    int n4 = C >> 2;
    int tail = C & 3;
    int tgt = g_tm[row];

    float4 v[8];
    float m = -INFINITY;
    float tval = 0.f;
    #pragma unroll
    for (int u = 0; u < 8; u++) {
        int k = lane + u * 32;
        if (k < n4) {
            v[u] = rp[k];
            int j = 4 * k;
            m = fmaxf(m, fmaxf(fmaxf(v[u].x, v[u].y), fmaxf(v[u].z, v[u].w)));
            if (tgt >= j && tgt < j + 4) {
                float t4[4] = {v[u].x, v[u].y, v[u].z, v[u].w};
                tval = t4[tgt - j];
            }
        }
    }
    float tv = 0.f; int tj = -1;
    if (tail && lane < tail) {
        tj = 4 * n4 + lane;
        tv = rowp[tj];
        m = fmaxf(m, tv);
        if (tj == tgt) tval = tv;
    }
    #pragma unroll
    for (int o = 16; o; o >>= 1) {
        m = fmaxf(m, __shfl_xor_sync(FULLMASK, m, o));
        tval += __shfl_xor_sync(FULLMASK, tval, o);
    }

    float s = 0.f;
    #pragma unroll
    for (int u = 0; u < 8; u++) {
        int k = lane + u * 32;
        if (k < n4) {
            s += __expf(v[u].x - m) + __expf(v[u].y - m)
               + __expf(v[u].z - m) + __expf(v[u].w - m);
        }
    }
    if (tj >= 0) s += __expf(tv - m);
    #pragma unroll
    for (int o = 16; o; o >>= 1) s += __shfl_xor_sync(FULLMASK, s, o);

    if (lane == 0)
        g_ce_u[row] = m + logf(s) - tval;
}

// ---- deterministic final reduction ------------------------------------------
__global__ void k_reduce(int Bx, int N, float* __restrict__ out) {
    __shared__ float sh[1024];
    __shared__ float lx_s;
    int tid = threadIdx.x;

    float a = 0.f;
    for (int i = tid; i < Bx; i += 1024) a += g_ce_x[i];
    sh[tid] = a;
    __syncthreads();
    for (int o = 512; o; o >>= 1) {
        if (tid < o) sh[tid] += sh[tid + o];
        __syncthreads();
    }
    if (tid == 0) lx_s = sh[0];
    __syncthreads();

    float b = 0.f;
    for (int i = tid; i < N; i += 1024) b += g_ce_u[i];
    sh[tid] = b;
    __syncthreads();
    for (int o = 512; o; o >>= 1) {
        if (tid < o) sh[tid] += sh[tid + o];
        __syncthreads();
    }
    if (tid == 0) {
        float Lx = lx_s / (float)Bx;
        float Lu = sh[0] / (float)N;
        out[0] = Lx + Lu;  // LAMBDA_U = 1.0
        out[1] = Lx;
        out[2] = Lu;
    }
}

// ---------------------------------------------------------------------------
extern "C" void kernel_launch(void* const* d_in, const int* in_sizes, int n_in,
                              void* d_out, int out_size) {
    const float* lx  = (const float*)d_in[0];
    const float* lwu = (const float*)d_in[1];
    const float* lsu = (const float*)d_in[2];
    const int*   tx  = (const int*)d_in[3];
    const float* gtp = (const float*)d_in[4];
    // d_in[5] = t (unused)

    int Bx = in_sizes[3];
    int C  = in_sizes[4];
    int N  = in_sizes[1] / C;
    int nseg = (N + SEG - 1) / SEG;

    float* out = (float*)d_out;

    int rows = N + Bx;
    int blk_rows = (rows + WPB - 1) / WPB;
    int blk_su   = (N + WPB - 1) / WPB;

    k_rows<<<blk_rows, WPB * 32>>>(lwu, lx, tx, C, N, Bx, out + 3);
    k_seghist<<<nseg, SEG>>>(N, C);
    k_scan<<<C, SEG>>>(nseg, gtp);
    k_rank<<<nseg, SEG>>>(N);
    k_su<<<blk_su, WPB * 32>>>(lsu, C, N);
    k_reduce<<<1, 1024>>>(Bx, N, out);
}

// round 4
// speedup vs baseline: 1.7244x; 1.0679x over previous
#include <cuda_runtime.h>
#include <math.h>

// ---------------------------------------------------------------------------
// CReST loss. Warp-per-row softmax (no barriers), match_any-based ranking.
//   out[0]=loss, out[1]=Lx, out[2]=Lu, out[3..3+N)=max_probs
// ---------------------------------------------------------------------------

#define FULLMASK 0xffffffffu
#define MAXC 1024
#define SEG 256
#define MAXN 65536
#define NSEG_MAX (MAXN / SEG)
#define MAXBX 32768
#define WPB 8              // warps per block in row kernels

__device__ int           g_tm[MAXN];
__device__ unsigned char g_mask[MAXN];
__device__ float         g_ce_x[MAXBX];
__device__ float         g_ce_u[MAXN];
__device__ int           g_seg_counts[NSEG_MAX][MAXC];
__device__ int           g_seg_off[NSEG_MAX][MAXC];
__device__ int           g_bn[MAXC];

// ---- fused kernel: wu rows (maxp + t_m) and x rows (supervised CE) ---------
__global__ void k_rows(const float* __restrict__ lwu,
                       const float* __restrict__ lx,
                       const int* __restrict__ tgts,
                       int C, int N, int Bx,
                       float* __restrict__ maxp_out) {
    int lane = threadIdx.x & 31;
    int gw = blockIdx.x * WPB + (threadIdx.x >> 5);
    int n4 = C >> 2;
    int tail = C & 3;

    if (gw < N) {
        // ---- weak-aug row: max_probs + pseudo target ----
        const float* rowp = lwu + (size_t)gw * C;
        const float4* rp = (const float4*)rowp;

        float4 v[8];
        float bv = -INFINITY;
        int bi = 0x3fffffff;
        #pragma unroll
        for (int u = 0; u < 8; u++) {
            int k = lane + u * 32;
            if (k < n4) {
                v[u] = __ldcs(rp + k);
                int j = 4 * k;
                if (v[u].x > bv) { bv = v[u].x; bi = j; }
                if (v[u].y > bv) { bv = v[u].y; bi = j + 1; }
                if (v[u].z > bv) { bv = v[u].z; bi = j + 2; }
                if (v[u].w > bv) { bv = v[u].w; bi = j + 3; }
            }
        }
        float tv = -INFINITY; int tj = -1;
        if (tail && lane < tail) {
            tj = 4 * n4 + lane;
            tv = __ldcs(rowp + tj);
            if (tv > bv) { bv = tv; bi = tj; }
        }

        // butterfly (val,idx) reduce, first-index tie-break
        #pragma unroll
        for (int o = 16; o; o >>= 1) {
            float ov = __shfl_xor_sync(FULLMASK, bv, o);
            int   oi = __shfl_xor_sync(FULLMASK, bi, o);
            if (ov > bv || (ov == bv && oi < bi)) { bv = ov; bi = oi; }
        }
        float maxv = bv;

        float s = 0.f;
        #pragma unroll
        for (int u = 0; u < 8; u++) {
            int k = lane + u * 32;
            if (k < n4) {
                s += __expf(v[u].x - maxv) + __expf(v[u].y - maxv)
                   + __expf(v[u].z - maxv) + __expf(v[u].w - maxv);
            }
        }
        if (tj >= 0) s += __expf(tv - maxv);
        #pragma unroll
        for (int o = 16; o; o >>= 1) s += __shfl_xor_sync(FULLMASK, s, o);

        if (lane == 0) {
            float maxp = 1.0f / s;  // exp(maxv - lse)
            maxp_out[gw] = maxp;
            g_tm[gw] = (maxp >= 0.95f) ? bi : 0;
        }
    } else if (gw < N + Bx) {
        // ---- supervised row: CE vs targets ----
        int row = gw - N;
        const float* rowp = lx + (size_t)row * C;
        const float4* rp = (const float4*)rowp;
        int tgt = tgts[row];

        float4 v[8];
        float m = -INFINITY;
        float tval = 0.f;
        #pragma unroll
        for (int u = 0; u < 8; u++) {
            int k = lane + u * 32;
            if (k < n4) {
                v[u] = __ldcs(rp + k);
                int j = 4 * k;
                m = fmaxf(m, fmaxf(fmaxf(v[u].x, v[u].y), fmaxf(v[u].z, v[u].w)));
                if (tgt >= j && tgt < j + 4) {
                    float t4[4] = {v[u].x, v[u].y, v[u].z, v[u].w};
                    tval = t4[tgt - j];
                }
            }
        }
        float tv = 0.f; int tj = -1;
        if (tail && lane < tail) {
            tj = 4 * n4 + lane;
            tv = __ldcs(rowp + tj);
            m = fmaxf(m, tv);
            if (tj == tgt) tval = tv;
        }
        #pragma unroll
        for (int o = 16; o; o >>= 1) {
            m = fmaxf(m, __shfl_xor_sync(FULLMASK, m, o));
            tval += __shfl_xor_sync(FULLMASK, tval, o);  // exactly one lane nonzero
        }

        float s = 0.f;
        #pragma unroll
        for (int u = 0; u < 8; u++) {
            int k = lane + u * 32;
            if (k < n4) {
                s += __expf(v[u].x - m) + __expf(v[u].y - m)
                   + __expf(v[u].z - m) + __expf(v[u].w - m);
            }
        }
        if (tj >= 0) s += __expf(tv - m);
        #pragma unroll
        for (int o = 16; o; o >>= 1) s += __shfl_xor_sync(FULLMASK, s, o);

        if (lane == 0)
            g_ce_x[row] = m + logf(s) - tval;
    }
}

// ---- per-segment class histograms -------------------------------------------
__global__ void k_seghist(int N, int C) {
    __shared__ int h[MAXC];
    for (int c = threadIdx.x; c < C; c += blockDim.x) h[c] = 0;
    __syncthreads();
    int row = blockIdx.x * SEG + threadIdx.x;
    if (row < N) atomicAdd(&h[g_tm[row]], 1);
    __syncthreads();
    for (int c = threadIdx.x; c < C; c += blockDim.x)
        g_seg_counts[blockIdx.x][c] = h[c];
}

// ---- per-class exclusive scan over segments + bn ----------------------------
__global__ void k_scan(int nseg, const float* __restrict__ gtp) {
    int c = blockIdx.x;
    int s = threadIdx.x;
    __shared__ int sh[SEG];

    int v = (s < nseg) ? g_seg_counts[s][c] : 0;
    sh[s] = v;
    __syncthreads();

    #pragma unroll
    for (int o = 1; o < SEG; o <<= 1) {
        int t = (s >= o) ? sh[s - o] : 0;
        __syncthreads();
        sh[s] += t;
        __syncthreads();
    }
    int incl = sh[s];
    if (s < nseg) g_seg_off[s][c] = incl - v;   // exclusive
    if (s == SEG - 1) {
        // round half-to-even, matching jnp.round
        g_bn[c] = (int)rintf((float)incl * gtp[c]);
    }
}

// ---- stable within-class rank + rebalance mask ------------------------------
// match_any within warp (lane order == index order -> stable rank), per-warp
// class histograms in shared for the cross-warp offset. Replaces O(SEG^2) loop.
__global__ void k_rank(int N) {
    __shared__ unsigned short whist[WPB][MAXC];   // 8 x 1024 x 2B = 16KB
    int r = threadIdx.x;
    int w = r >> 5;
    int lane = r & 31;
    int row = blockIdx.x * SEG + r;

    // zero histograms (as 32-bit words)
    unsigned int* hz = (unsigned int*)whist;
    #pragma unroll
    for (int i = r; i < WPB * MAXC / 2; i += SEG) hz[i] = 0u;

    int myc = (row < N) ? g_tm[row] : -1;

    unsigned int mmask = __match_any_sync(FULLMASK, myc);
    int within = __popc(mmask & ((1u << lane) - 1u));
    int leader = __ffs(mmask) - 1;

    __syncthreads();   // zeroing done before leader stores
    if (lane == leader && myc >= 0)
        whist[w][myc] = (unsigned short)__popc(mmask);
    __syncthreads();

    if (row < N) {
        int cross = 0;
        #pragma unroll
        for (int j = 0; j < WPB; j++)
            if (j < w) cross += whist[j][myc];
        int rank = g_seg_off[blockIdx.x][myc] + cross + within;
        g_mask[row] = (unsigned char)((myc != 0) && (rank < g_bn[myc]));
    }
}

// ---- unsupervised CE, warp per row, skip masked-out rows --------------------
__global__ void k_su(const float* __restrict__ lsu, int C, int N) {
    int lane = threadIdx.x & 31;
    int row = blockIdx.x * WPB + (threadIdx.x >> 5);
    if (row >= N) return;
    if (!g_mask[row]) {
        if (lane == 0) g_ce_u[row] = 0.f;
        return;  // per-warp exit, no barriers in this kernel
    }
    const float* rowp = lsu + (size_t)row * C;
    const float4* rp = (const float4*)rowp;
    int n4 = C >> 2;
    int tail = C & 3;
    int tgt = g_tm[row];

    float4 v[8];
    float m = -INFINITY;
    float tval = 0.f;
    #pragma unroll
    for (int u = 0; u < 8; u++) {
        int k = lane + u * 32;
        if (k < n4) {
            v[u] = __ldcs(rp + k);
            int j = 4 * k;
            m = fmaxf(m, fmaxf(fmaxf(v[u].x, v[u].y), fmaxf(v[u].z, v[u].w)));
            if (tgt >= j && tgt < j + 4) {
                float t4[4] = {v[u].x, v[u].y, v[u].z, v[u].w};
                tval = t4[tgt - j];
            }
        }
    }
    float tv = 0.f; int tj = -1;
    if (tail && lane < tail) {
        tj = 4 * n4 + lane;
        tv = __ldcs(rowp + tj);
        m = fmaxf(m, tv);
        if (tj == tgt) tval = tv;
    }
    #pragma unroll
    for (int o = 16; o; o >>= 1) {
        m = fmaxf(m, __shfl_xor_sync(FULLMASK, m, o));
        tval += __shfl_xor_sync(FULLMASK, tval, o);
    }

    float s = 0.f;
    #pragma unroll
    for (int u = 0; u < 8; u++) {
        int k = lane + u * 32;
        if (k < n4) {
            s += __expf(v[u].x - m) + __expf(v[u].y - m)
               + __expf(v[u].z - m) + __expf(v[u].w - m);
        }
    }
    if (tj >= 0) s += __expf(tv - m);
    #pragma unroll
    for (int o = 16; o; o >>= 1) s += __shfl_xor_sync(FULLMASK, s, o);

    if (lane == 0)
        g_ce_u[row] = m + logf(s) - tval;
}

// ---- deterministic final reduction ------------------------------------------
__global__ void k_reduce(int Bx, int N, float* __restrict__ out) {
    __shared__ float sh[1024];
    __shared__ float lx_s;
    int tid = threadIdx.x;

    float a = 0.f;
    for (int i = tid; i < Bx; i += 1024) a += g_ce_x[i];
    sh[tid] = a;
    __syncthreads();
    for (int o = 512; o; o >>= 1) {
        if (tid < o) sh[tid] += sh[tid + o];
        __syncthreads();
    }
    if (tid == 0) lx_s = sh[0];
    __syncthreads();

    float b = 0.f;
    for (int i = tid; i < N; i += 1024) b += g_ce_u[i];
    sh[tid] = b;
    __syncthreads();
    for (int o = 512; o; o >>= 1) {
        if (tid < o) sh[tid] += sh[tid + o];
        __syncthreads();
    }
    if (tid == 0) {
        float Lx = lx_s / (float)Bx;
        float Lu = sh[0] / (float)N;
        out[0] = Lx + Lu;  // LAMBDA_U = 1.0
        out[1] = Lx;
        out[2] = Lu;
    }
}

// ---------------------------------------------------------------------------
extern "C" void kernel_launch(void* const* d_in, const int* in_sizes, int n_in,
                              void* d_out, int out_size) {
    const float* lx  = (const float*)d_in[0];
    const float* lwu = (const float*)d_in[1];
    const float* lsu = (const float*)d_in[2];
    const int*   tx  = (const int*)d_in[3];
    const float* gtp = (const float*)d_in[4];
    // d_in[5] = t (unused)

    int Bx = in_sizes[3];
    int C  = in_sizes[4];
    int N  = in_sizes[1] / C;
    int nseg = (N + SEG - 1) / SEG;

    float* out = (float*)d_out;

    int rows = N + Bx;
    int blk_rows = (rows + WPB - 1) / WPB;
    int blk_su   = (N + WPB - 1) / WPB;

    k_rows<<<blk_rows, WPB * 32>>>(lwu, lx, tx, C, N, Bx, out + 3);
    k_seghist<<<nseg, SEG>>>(N, C);
    k_scan<<<C, SEG>>>(nseg, gtp);
    k_rank<<<nseg, SEG>>>(N);
    k_su<<<blk_su, WPB * 32>>>(lsu, C, N);
    k_reduce<<<1, 1024>>>(Bx, N, out);
}